// round 13
// baseline (speedup 1.0000x reference)
#include <cuda_runtime.h>

// Problem constants
#define B_      16
#define C_      512
#define HW_     4096
#define INNER_  256
#define HW4     1024        // HW_/4 (float4 units per channel)

// Pass-kernel tiling: lane owns 2 float4 of one channel; warp covers 64 float4
#define NTILE   4           // CTA tiles per (b,g): 4 CTAs x 4 warps = 16 warp-tiles
#define NCGRP   32          // channel groups per batch (16 ch each)
#define CG      16          // C_ / NCGRP
#define NT      128         // threads per pass CTA
#define NWARP   4           // NT/32
#define NPART   16          // warp-tile partials per (b,c)

// weff k-split
#define KCH     32          // k chunks
#define KPER    (INNER_/KCH)   // 8 rows per chunk

// ---------------------------------------------------------------------------
// Scratch (static device globals; fully overwritten every call -> deterministic)
// ---------------------------------------------------------------------------
__device__ __align__(16) float g_cm_part [B_*NCGRP*HW_];   // 8 MB
__device__ __align__(16) float g_ctx_part[B_*NCGRP*HW_];   // 8 MB
__device__ __align__(16) float g_cm      [B_*HW_];         // exp(cm_raw), UNNORMALIZED
__device__ __align__(16) float g_sigctx  [B_*HW_];         // sigmoid(spatial ctx)
__device__ __align__(16) float g_xsum_part[B_*C_*NPART];   // 0.5 MB
__device__ __align__(16) float g_xw_part  [B_*C_*NPART];   // 0.5 MB
__device__ __align__(16) float g_xmean[B_*C_];
__device__ __align__(16) float g_xw   [B_*C_];             // unnormalized x@exp(cm)
__device__ __align__(16) float g_a    [B_*INNER_];         // Wsq@xmean (pre-softmax)
__device__ __align__(16) float g_ctx  [B_*INNER_];         // Wcv@(xw/Z)
__device__ __align__(16) float g_z    [B_*C_];             // Wcz@ctx (pre-LN)
__device__ __align__(16) float g_weff_part[KCH*B_*C_];     // k-chunk partials (UNNORM)
__device__ float g_Zs_part[KCH*B_];                        // spatial-softmax Z partials
__device__ float g_Zc_part[B_*4];                          // channel-softmax Z partials
__device__ float g_mask[B_*C_];

// ---------------------------------------------------------------------------
// Reductions
// ---------------------------------------------------------------------------
__device__ __forceinline__ float warpReduceSum(float v) {
    #pragma unroll
    for (int o = 16; o; o >>= 1) v += __shfl_down_sync(0xffffffffu, v, o);
    return v;
}

__device__ __forceinline__ float blockReduceSum(float v) {
    __shared__ float s[17];
    const int lane = threadIdx.x & 31, wid = threadIdx.x >> 5;
    v = warpReduceSum(v);
    if (lane == 0) s[wid] = v;
    __syncthreads();
    if (wid == 0) {
        float t = (lane < (int)(blockDim.x >> 5)) ? s[lane] : 0.0f;
        #pragma unroll
        for (int o = 8; o; o >>= 1) t += __shfl_down_sync(0xffffffffu, t, o);
        if (lane == 0) s[16] = t;
    }
    __syncthreads();
    float r = s[16];
    __syncthreads();
    return r;
}

__device__ __forceinline__ float dot4(float4 a, float4 b) {
    return fmaf(a.x, b.x, fmaf(a.y, b.y, fmaf(a.z, b.z, a.w * b.w)));
}

// ---------------------------------------------------------------------------
// Pass 1: stream x once -> cm_raw partials (per pixel) + xsum partials (per ch)
// grid: (NTILE*NCGRP, B_) = (128, 16) = 2048 CTAs, block 128 (262K threads).
// Each warp covers 64 float4 (256 px) per channel: lane holds 2 float4.
// ---------------------------------------------------------------------------
__global__ __launch_bounds__(NT)
void k_pass1(const float* __restrict__ x, const float* __restrict__ Wcq) {
    const int b    = blockIdx.y;
    const int tile = blockIdx.x >> 5;   // /NCGRP  (0..3)
    const int g    = blockIdx.x & 31;
    const int tid  = threadIdx.x;
    const int lane = tid & 31, warp = tid >> 5;
    const int wtile = tile*NWARP + warp;   // 0..15

    __shared__ float s_w[CG];
    if (tid < CG) s_w[tid] = Wcq[g*CG + tid];
    __syncthreads();

    const float4* x4 = reinterpret_cast<const float4*>(x);
    const int fbase = (b*C_ + g*CG)*HW4 + wtile*64 + lane;

    float4 a0 = make_float4(0.f,0.f,0.f,0.f);
    float4 a1 = make_float4(0.f,0.f,0.f,0.f);
    #pragma unroll 4
    for (int ci = 0; ci < CG; ci++) {
        float4 v0 = x4[fbase + ci*HW4];
        float4 v1 = x4[fbase + ci*HW4 + 32];
        float  q  = s_w[ci];
        a0.x = fmaf(q, v0.x, a0.x); a0.y = fmaf(q, v0.y, a0.y);
        a0.z = fmaf(q, v0.z, a0.z); a0.w = fmaf(q, v0.w, a0.w);
        a1.x = fmaf(q, v1.x, a1.x); a1.y = fmaf(q, v1.y, a1.y);
        a1.z = fmaf(q, v1.z, a1.z); a1.w = fmaf(q, v1.w, a1.w);
        float s = ((v0.x+v0.y)+(v0.z+v0.w)) + ((v1.x+v1.y)+(v1.z+v1.w));
        s = warpReduceSum(s);
        if (lane == 0)
            g_xsum_part[(b*C_ + g*CG + ci)*NPART + wtile] = s;
    }
    float4* cmp = reinterpret_cast<float4*>(g_cm_part) + (b*NCGRP + g)*HW4 + wtile*64 + lane;
    cmp[0]  = a0;
    cmp[32] = a1;
}

// ---------------------------------------------------------------------------
// Red 1 (wide): grid (5, B_), block 256.
//   bx<4 : reduce cm partials -> g_cm = exp(raw), per-CTA expsum -> g_Zc_part
//   bx==4: reduce xsum partials -> g_xmean
// ---------------------------------------------------------------------------
__global__ __launch_bounds__(256)
void k_red1() {
    const int b  = blockIdx.y;
    const int bx = blockIdx.x;
    const int tid = threadIdx.x;

    if (bx < 4) {
        const int pix4 = bx*256 + tid;       // float4 index in [0,HW4)
        const float4* cp = reinterpret_cast<const float4*>(g_cm_part);
        float4 s = make_float4(0.f, 0.f, 0.f, 0.f);
        #pragma unroll
        for (int g = 0; g < NCGRP; g++) {
            float4 v = cp[(b*NCGRP + g)*HW4 + pix4];
            s.x += v.x; s.y += v.y; s.z += v.z; s.w += v.w;
        }
        float4 e;
        e.x = __expf(s.x); e.y = __expf(s.y);
        e.z = __expf(s.z); e.w = __expf(s.w);
        reinterpret_cast<float4*>(g_cm)[b*HW4 + pix4] = e;
        float zs = blockReduceSum((e.x + e.y) + (e.z + e.w));
        if (tid == 0) g_Zc_part[b*4 + bx] = zs;
    } else {
        for (int c = tid; c < C_; c += 256) {
            const float4* p = reinterpret_cast<const float4*>(
                g_xsum_part + (b*C_ + c)*NPART);
            float s = 0.f;
            #pragma unroll
            for (int i = 0; i < NPART/4; i++) {
                float4 v = p[i];
                s += (v.x + v.y) + (v.z + v.w);
            }
            g_xmean[b*C_ + c] = s * (1.0f/(float)HW_);
        }
    }
}

// ---------------------------------------------------------------------------
// GEMM a = Wsq(256x512) @ xmean(512 x 16batches). grid 32, block 256.
// ---------------------------------------------------------------------------
__global__ __launch_bounds__(256)
void k_gemm_a(const float* __restrict__ Wsq) {
    const int tid = threadIdx.x;
    const int lane = tid & 31, warp = tid >> 5;
    __shared__ __align__(16) float s_xm[B_*C_];      // 32 KB

    float4* sm4 = reinterpret_cast<float4*>(s_xm);
    const float4* gm4 = reinterpret_cast<const float4*>(g_xmean);
    #pragma unroll
    for (int i = tid; i < B_*C_/4; i += 256) sm4[i] = gm4[i];
    __syncthreads();

    const int row = blockIdx.x*8 + warp;             // [0,256)
    const float4* wr = reinterpret_cast<const float4*>(Wsq + row*C_);
    float acc[B_];
    #pragma unroll
    for (int b = 0; b < B_; b++) acc[b] = 0.f;
    #pragma unroll
    for (int j = 0; j < C_/(4*32); j++) {
        float4 w4 = wr[lane + 32*j];
        #pragma unroll
        for (int b = 0; b < B_; b++)
            acc[b] += dot4(w4, sm4[b*(C_/4) + lane + 32*j]);
    }
    #pragma unroll
    for (int b = 0; b < B_; b++) {
        float r = warpReduceSum(acc[b]);
        if (lane == 0) g_a[b*INNER_ + row] = r;
    }
}

// ---------------------------------------------------------------------------
// weff partials, DEFERRED NORMALIZATION. grid (KCH, B_) = 512 CTAs, block 128.
// ---------------------------------------------------------------------------
__global__ __launch_bounds__(128)
void k_weff(const float* __restrict__ Wsv) {
    const int kc = blockIdx.x;
    const int b  = blockIdx.y;
    const int tid = threadIdx.x;
    __shared__ __align__(16) float s_e[KPER];

    if (tid < KPER)
        s_e[tid] = __expf(g_a[b*INNER_ + kc*KPER + tid]);
    __syncthreads();
    if (tid == 0) {
        float z = 0.f;
        #pragma unroll
        for (int k = 0; k < KPER; k++) z += s_e[k];
        g_Zs_part[kc*B_ + b] = z;
    }

    const float4* w4 = reinterpret_cast<const float4*>(Wsv);
    float4 acc = make_float4(0.f, 0.f, 0.f, 0.f);
    #pragma unroll
    for (int k = 0; k < KPER; k++) {
        float4 w = w4[(kc*KPER + k)*(C_/4) + tid];       // coalesced full row
        float  a = s_e[k];
        acc.x = fmaf(a, w.x, acc.x);
        acc.y = fmaf(a, w.y, acc.y);
        acc.z = fmaf(a, w.z, acc.z);
        acc.w = fmaf(a, w.w, acc.w);
    }
    reinterpret_cast<float4*>(g_weff_part)[(kc*B_ + b)*(C_/4) + tid] = acc;
}

// ---------------------------------------------------------------------------
// Pass 2: stream x again -> xw partials (unnormalized, vs exp(cm)) + ctx partials
// Same warp-tiling as pass1; cm held in registers across the channel loop.
// ---------------------------------------------------------------------------
__global__ __launch_bounds__(NT)
void k_pass2(const float* __restrict__ x) {
    const int b    = blockIdx.y;
    const int tile = blockIdx.x >> 5;
    const int g    = blockIdx.x & 31;
    const int tid  = threadIdx.x;
    const int lane = tid & 31, warp = tid >> 5;
    const int wtile = tile*NWARP + warp;

    __shared__ float s_w[CG];
    __shared__ float s_invZs;
    if (tid == 0) {
        float z = 0.f;
        #pragma unroll
        for (int p = 0; p < KCH; p++) z += g_Zs_part[p*B_ + b];
        s_invZs = 1.0f / z;
    }
    __syncthreads();
    if (tid < CG) {
        float s = 0.f;
        #pragma unroll
        for (int p = 0; p < KCH; p++)
            s += g_weff_part[(p*B_ + b)*C_ + g*CG + tid];
        s_w[tid] = s * s_invZs;
    }
    __syncthreads();

    const float4* x4 = reinterpret_cast<const float4*>(x);
    const int fbase = (b*C_ + g*CG)*HW4 + wtile*64 + lane;
    const float4* cmp = reinterpret_cast<const float4*>(g_cm) + b*HW4 + wtile*64 + lane;
    const float4 cm0 = cmp[0];
    const float4 cm1 = cmp[32];

    float4 c0 = make_float4(0.f,0.f,0.f,0.f);
    float4 c1 = make_float4(0.f,0.f,0.f,0.f);
    #pragma unroll 4
    for (int ci = 0; ci < CG; ci++) {
        float4 v0 = x4[fbase + ci*HW4];
        float4 v1 = x4[fbase + ci*HW4 + 32];
        float  w  = s_w[ci];
        c0.x = fmaf(w, v0.x, c0.x); c0.y = fmaf(w, v0.y, c0.y);
        c0.z = fmaf(w, v0.z, c0.z); c0.w = fmaf(w, v0.w, c0.w);
        c1.x = fmaf(w, v1.x, c1.x); c1.y = fmaf(w, v1.y, c1.y);
        c1.z = fmaf(w, v1.z, c1.z); c1.w = fmaf(w, v1.w, c1.w);
        float t = dot4(v0, cm0) + dot4(v1, cm1);
        t = warpReduceSum(t);
        if (lane == 0)
            g_xw_part[(b*C_ + g*CG + ci)*NPART + wtile] = t;
    }
    float4* cxp = reinterpret_cast<float4*>(g_ctx_part) + (b*NCGRP + g)*HW4 + wtile*64 + lane;
    cxp[0]  = c0;
    cxp[32] = c1;
}

// ---------------------------------------------------------------------------
// Red 2 (wide): grid (5, B_), block 256.
// ---------------------------------------------------------------------------
__global__ __launch_bounds__(256)
void k_red2() {
    const int b  = blockIdx.y;
    const int bx = blockIdx.x;
    const int tid = threadIdx.x;

    if (bx < 4) {
        const int pix4 = bx*256 + tid;
        const float4* cp = reinterpret_cast<const float4*>(g_ctx_part);
        float4 s = make_float4(0.f, 0.f, 0.f, 0.f);
        #pragma unroll
        for (int g = 0; g < NCGRP; g++) {
            float4 v = cp[(b*NCGRP + g)*HW4 + pix4];
            s.x += v.x; s.y += v.y; s.z += v.z; s.w += v.w;
        }
        float4 r;
        r.x = 1.0f/(1.0f + __expf(-s.x));
        r.y = 1.0f/(1.0f + __expf(-s.y));
        r.z = 1.0f/(1.0f + __expf(-s.z));
        r.w = 1.0f/(1.0f + __expf(-s.w));
        reinterpret_cast<float4*>(g_sigctx)[b*HW4 + pix4] = r;
    } else {
        for (int c = tid; c < C_; c += 256) {
            const float4* p = reinterpret_cast<const float4*>(
                g_xw_part + (b*C_ + c)*NPART);
            float s = 0.f;
            #pragma unroll
            for (int i = 0; i < NPART/4; i++) {
                float4 v = p[i];
                s += (v.x + v.y) + (v.z + v.w);
            }
            g_xw[b*C_ + c] = s;
        }
    }
}

// ---------------------------------------------------------------------------
// GEMM ctx = Wcv(256x512) @ (xw/Z)(512 x 16). grid 32, block 256.
// ---------------------------------------------------------------------------
__global__ __launch_bounds__(256)
void k_gemm_ctx(const float* __restrict__ Wcv) {
    const int tid = threadIdx.x;
    const int lane = tid & 31, warp = tid >> 5;
    __shared__ __align__(16) float s_xw[B_*C_];      // 32 KB
    __shared__ float s_invZ[B_];

    if (tid < B_)
        s_invZ[tid] = 1.0f / (g_Zc_part[tid*4+0] + g_Zc_part[tid*4+1] +
                              g_Zc_part[tid*4+2] + g_Zc_part[tid*4+3]);
    __syncthreads();

    float4* sm4 = reinterpret_cast<float4*>(s_xw);
    const float4* gm4 = reinterpret_cast<const float4*>(g_xw);
    #pragma unroll
    for (int i = tid; i < B_*C_/4; i += 256) {
        float4 v = gm4[i];
        float z = s_invZ[i >> 7];       // i*4/512
        v.x *= z; v.y *= z; v.z *= z; v.w *= z;
        sm4[i] = v;
    }
    __syncthreads();

    const int row = blockIdx.x*8 + warp;
    const float4* wr = reinterpret_cast<const float4*>(Wcv + row*C_);
    float acc[B_];
    #pragma unroll
    for (int b = 0; b < B_; b++) acc[b] = 0.f;
    #pragma unroll
    for (int j = 0; j < C_/(4*32); j++) {
        float4 w4 = wr[lane + 32*j];
        #pragma unroll
        for (int b = 0; b < B_; b++)
            acc[b] += dot4(w4, sm4[b*(C_/4) + lane + 32*j]);
    }
    #pragma unroll
    for (int b = 0; b < B_; b++) {
        float r = warpReduceSum(acc[b]);
        if (lane == 0) g_ctx[b*INNER_ + row] = r;
    }
}

// ---------------------------------------------------------------------------
// GEMM z = Wcz(512x256) @ ctx(256 x 16). grid 64, block 256.
// ---------------------------------------------------------------------------
__global__ __launch_bounds__(256)
void k_gemm_z(const float* __restrict__ Wcz) {
    const int tid = threadIdx.x;
    const int lane = tid & 31, warp = tid >> 5;
    __shared__ __align__(16) float s_ctx[B_*INNER_];   // 16 KB

    float4* sm4 = reinterpret_cast<float4*>(s_ctx);
    const float4* gm4 = reinterpret_cast<const float4*>(g_ctx);
    #pragma unroll
    for (int i = tid; i < B_*INNER_/4; i += 256) sm4[i] = gm4[i];
    __syncthreads();

    const int row = blockIdx.x*8 + warp;               // [0,512)
    const float4* wr = reinterpret_cast<const float4*>(Wcz + row*INNER_);
    float acc[B_];
    #pragma unroll
    for (int b = 0; b < B_; b++) acc[b] = 0.f;
    #pragma unroll
    for (int j = 0; j < INNER_/(4*32); j++) {
        float4 w4 = wr[lane + 32*j];
        #pragma unroll
        for (int b = 0; b < B_; b++)
            acc[b] += dot4(w4, sm4[b*(INNER_/4) + lane + 32*j]);
    }
    #pragma unroll
    for (int b = 0; b < B_; b++) {
        float r = warpReduceSum(acc[b]);
        if (lane == 0) g_z[b*C_ + row] = r;
    }
}

// ---------------------------------------------------------------------------
// LayerNorm + sigmoid -> mask. grid B_, block 512.
// ---------------------------------------------------------------------------
__global__ __launch_bounds__(512)
void k_ln(const float* __restrict__ gamma, const float* __restrict__ beta) {
    const int b = blockIdx.x;
    const int tid = threadIdx.x;
    float z = g_z[b*C_ + tid];
    float mu  = blockReduceSum(z) * (1.0f/(float)C_);
    float m2  = blockReduceSum(z*z) * (1.0f/(float)C_);
    float var = m2 - mu*mu;
    float zn  = (z - mu) * rsqrtf(var + 1e-5f) * gamma[tid] + beta[tid];
    g_mask[b*C_ + tid] = 1.0f/(1.0f + __expf(-zn));
}

// ---------------------------------------------------------------------------
// Final: out = x * (mask[b,c] + sig_ctx[b,n])
// ---------------------------------------------------------------------------
__global__ __launch_bounds__(256)
void k_final(const float* __restrict__ x, float* __restrict__ out) {
    const float4* x4  = reinterpret_cast<const float4*>(x);
    float4*       o4  = reinterpret_cast<float4*>(out);
    const float4* sc4 = reinterpret_cast<const float4*>(g_sigctx);
    const int total4 = B_*C_*HW4;
    for (int i = blockIdx.x*blockDim.x + threadIdx.x; i < total4;
         i += gridDim.x*blockDim.x) {
        const int n4 = i & (HW4 - 1);
        const int bc = i >> 10;          // b*512 + c
        const int b  = bc >> 9;
        const float  m = g_mask[bc];     // warp-uniform -> single sector
        const float4 s = sc4[(b << 10) + n4];
        float4 v = x4[i];
        float4 r;
        r.x = v.x*(m + s.x);
        r.y = v.y*(m + s.y);
        r.z = v.z*(m + s.z);
        r.w = v.w*(m + s.w);
        o4[i] = r;
    }
}

// ---------------------------------------------------------------------------
// Launch
// ---------------------------------------------------------------------------
extern "C" void kernel_launch(void* const* d_in, const int* in_sizes, int n_in,
                              void* d_out, int out_size) {
    const float* x     = (const float*)d_in[0];
    const float* Wsq   = (const float*)d_in[1];
    const float* Wsv   = (const float*)d_in[2];
    const float* Wcq   = (const float*)d_in[3];
    const float* Wcv   = (const float*)d_in[4];
    const float* Wcz   = (const float*)d_in[5];
    const float* gamma = (const float*)d_in[6];
    const float* beta  = (const float*)d_in[7];
    float* out = (float*)d_out;

    dim3 gpass(NTILE*NCGRP, B_);   // 128 x 16 = 2048 CTAs
    dim3 gred(5, B_);              // 80 CTAs
    dim3 gweff(KCH, B_);           // 512 CTAs
    k_pass1   <<<gpass, NT>>>(x, Wcq);
    k_red1    <<<gred, 256>>>();
    k_gemm_a  <<<32, 256>>>(Wsq);
    k_weff    <<<gweff, 128>>>(Wsv);
    k_pass2   <<<gpass, NT>>>(x);
    k_red2    <<<gred, 256>>>();
    k_gemm_ctx<<<32, 256>>>(Wcv);
    k_gemm_z  <<<64, 256>>>(Wcz);
    k_ln      <<<B_, 512>>>(gamma, beta);
    k_final   <<<8192, 256>>>(x, out);
}

// round 14
// speedup vs baseline: 1.0270x; 1.0270x over previous
#include <cuda_runtime.h>

// Problem constants
#define B_      16
#define C_      512
#define HW_     4096
#define INNER_  256
#define HW4     1024        // HW_/4 (float4 units per channel)

// Pass-kernel tiling: lane owns 2 float4 of one channel; warp covers 64 float4
#define NTILE   4           // CTA tiles per (b,g): 4 CTAs x 4 warps = 16 warp-tiles
#define NCGRP   16          // channel groups per batch (32 ch each)
#define CG      32          // C_ / NCGRP
#define NT      128         // threads per pass CTA
#define NWARP   4           // NT/32
#define NPART   16          // warp-tile partials per (b,c)

// weff k-split (one chunk per k_gemm_aw CTA)
#define KCH     32          // k chunks
#define KPER    (INNER_/KCH)   // 8 rows per chunk

// ---------------------------------------------------------------------------
// Scratch (static device globals; fully overwritten every call -> deterministic)
// ---------------------------------------------------------------------------
__device__ __align__(16) float g_cm_part [B_*NCGRP*HW_];   // 4 MB
__device__ __align__(16) float g_ctx_part[B_*NCGRP*HW_];   // 4 MB
__device__ __align__(16) float g_cm      [B_*HW_];         // exp(cm_raw), UNNORMALIZED
__device__ __align__(16) float g_sigctx  [B_*HW_];         // sigmoid(spatial ctx)
__device__ __align__(16) float g_xsum_part[B_*C_*NPART];   // 0.5 MB
__device__ __align__(16) float g_xw_part  [B_*C_*NPART];   // 0.5 MB
__device__ __align__(16) float g_xmean[B_*C_];
__device__ __align__(16) float g_xw   [B_*C_];             // unnormalized x@exp(cm)
__device__ __align__(16) float g_ctx  [B_*INNER_];         // Wcv@(xw/Z)
__device__ __align__(16) float g_z    [B_*C_];             // Wcz@ctx (pre-LN)
__device__ __align__(16) float g_weff_part[KCH*B_*C_];     // k-chunk partials (UNNORM)
__device__ float g_Zs_part[KCH*B_];                        // spatial-softmax Z partials
__device__ float g_Zc_part[B_*4];                          // channel-softmax Z partials
__device__ float g_mask[B_*C_];

// ---------------------------------------------------------------------------
// Reductions
// ---------------------------------------------------------------------------
__device__ __forceinline__ float warpReduceSum(float v) {
    #pragma unroll
    for (int o = 16; o; o >>= 1) v += __shfl_down_sync(0xffffffffu, v, o);
    return v;
}

__device__ __forceinline__ float blockReduceSum(float v) {
    __shared__ float s[17];
    const int lane = threadIdx.x & 31, wid = threadIdx.x >> 5;
    v = warpReduceSum(v);
    if (lane == 0) s[wid] = v;
    __syncthreads();
    if (wid == 0) {
        float t = (lane < (int)(blockDim.x >> 5)) ? s[lane] : 0.0f;
        #pragma unroll
        for (int o = 8; o; o >>= 1) t += __shfl_down_sync(0xffffffffu, t, o);
        if (lane == 0) s[16] = t;
    }
    __syncthreads();
    float r = s[16];
    __syncthreads();
    return r;
}

__device__ __forceinline__ float dot4(float4 a, float4 b) {
    return fmaf(a.x, b.x, fmaf(a.y, b.y, fmaf(a.z, b.z, a.w * b.w)));
}

// ---------------------------------------------------------------------------
// Pass 1: stream x once -> cm_raw partials (per pixel) + xsum partials (per ch)
// grid: (NTILE*NCGRP, B_) = (64, 16) = 1024 CTAs, block 128.
// Each warp covers 64 float4 (256 px) per channel: lane holds 2 float4.
// ---------------------------------------------------------------------------
__global__ __launch_bounds__(NT)
void k_pass1(const float* __restrict__ x, const float* __restrict__ Wcq) {
    const int b    = blockIdx.y;
    const int tile = blockIdx.x >> 4;   // /NCGRP  (0..3)
    const int g    = blockIdx.x & 15;
    const int tid  = threadIdx.x;
    const int lane = tid & 31, warp = tid >> 5;
    const int wtile = tile*NWARP + warp;   // 0..15

    __shared__ float s_w[CG];
    if (tid < CG) s_w[tid] = Wcq[g*CG + tid];
    __syncthreads();

    const float4* x4 = reinterpret_cast<const float4*>(x);
    const int fbase = (b*C_ + g*CG)*HW4 + wtile*64 + lane;

    float4 a0 = make_float4(0.f,0.f,0.f,0.f);
    float4 a1 = make_float4(0.f,0.f,0.f,0.f);
    #pragma unroll 4
    for (int ci = 0; ci < CG; ci++) {
        float4 v0 = x4[fbase + ci*HW4];
        float4 v1 = x4[fbase + ci*HW4 + 32];
        float  q  = s_w[ci];
        a0.x = fmaf(q, v0.x, a0.x); a0.y = fmaf(q, v0.y, a0.y);
        a0.z = fmaf(q, v0.z, a0.z); a0.w = fmaf(q, v0.w, a0.w);
        a1.x = fmaf(q, v1.x, a1.x); a1.y = fmaf(q, v1.y, a1.y);
        a1.z = fmaf(q, v1.z, a1.z); a1.w = fmaf(q, v1.w, a1.w);
        float s = ((v0.x+v0.y)+(v0.z+v0.w)) + ((v1.x+v1.y)+(v1.z+v1.w));
        s = warpReduceSum(s);
        if (lane == 0)
            g_xsum_part[(b*C_ + g*CG + ci)*NPART + wtile] = s;
    }
    float4* cmp = reinterpret_cast<float4*>(g_cm_part) + (b*NCGRP + g)*HW4 + wtile*64 + lane;
    cmp[0]  = a0;
    cmp[32] = a1;
}

// ---------------------------------------------------------------------------
// Red 1 (wide): grid (5, B_), block 256.
//   bx<4 : reduce cm partials -> g_cm = exp(raw), per-CTA expsum -> g_Zc_part
//   bx==4: reduce xsum partials -> g_xmean
// ---------------------------------------------------------------------------
__global__ __launch_bounds__(256)
void k_red1() {
    const int b  = blockIdx.y;
    const int bx = blockIdx.x;
    const int tid = threadIdx.x;

    if (bx < 4) {
        const int pix4 = bx*256 + tid;       // float4 index in [0,HW4)
        const float4* cp = reinterpret_cast<const float4*>(g_cm_part);
        float4 s = make_float4(0.f, 0.f, 0.f, 0.f);
        #pragma unroll
        for (int g = 0; g < NCGRP; g++) {
            float4 v = cp[(b*NCGRP + g)*HW4 + pix4];
            s.x += v.x; s.y += v.y; s.z += v.z; s.w += v.w;
        }
        float4 e;
        e.x = __expf(s.x); e.y = __expf(s.y);
        e.z = __expf(s.z); e.w = __expf(s.w);
        reinterpret_cast<float4*>(g_cm)[b*HW4 + pix4] = e;
        float zs = blockReduceSum((e.x + e.y) + (e.z + e.w));
        if (tid == 0) g_Zc_part[b*4 + bx] = zs;
    } else {
        for (int c = tid; c < C_; c += 256) {
            const float4* p = reinterpret_cast<const float4*>(
                g_xsum_part + (b*C_ + c)*NPART);
            float s = 0.f;
            #pragma unroll
            for (int i = 0; i < NPART/4; i++) {
                float4 v = p[i];
                s += (v.x + v.y) + (v.z + v.w);
            }
            g_xmean[b*C_ + c] = s * (1.0f/(float)HW_);
        }
    }
}

// ---------------------------------------------------------------------------
// MERGED GEMM-a + weff (deferred normalization), grid 32, block 256 (8 warps).
// Phase 1: each warp computes one a-row (Wsq[row,:] . xmean[b]) for all 16
//          batches (xmean in smem), exps into s_e[row_in_chunk][b].
// Phase 2: Zs partial per batch; then each thread accumulates 2 columns x 16
//          batches of the unnormalized weff partial over the CTA's 8 Wsv rows.
// Same 32-CTA width as before; k_weff kernel is eliminated.
// ---------------------------------------------------------------------------
__global__ __launch_bounds__(256)
void k_gemm_aw(const float* __restrict__ Wsq, const float* __restrict__ Wsv) {
    const int tid = threadIdx.x;
    const int lane = tid & 31, warp = tid >> 5;
    const int kc = blockIdx.x;                       // k-chunk = 8 rows
    __shared__ __align__(16) float s_xm[B_*C_];      // 32 KB
    __shared__ float s_e[KPER*B_];                   // exp(a) for this chunk

    float4* sm4 = reinterpret_cast<float4*>(s_xm);
    const float4* gm4 = reinterpret_cast<const float4*>(g_xmean);
    #pragma unroll
    for (int i = tid; i < B_*C_/4; i += 256) sm4[i] = gm4[i];
    __syncthreads();

    // Phase 1: warp w -> row kc*8 + w, all batches
    {
        const int row = kc*KPER + warp;              // [0,256)
        const float4* wr = reinterpret_cast<const float4*>(Wsq + row*C_);
        float acc[B_];
        #pragma unroll
        for (int b = 0; b < B_; b++) acc[b] = 0.f;
        #pragma unroll
        for (int j = 0; j < C_/(4*32); j++) {
            float4 w4 = wr[lane + 32*j];
            #pragma unroll
            for (int b = 0; b < B_; b++)
                acc[b] += dot4(w4, sm4[b*(C_/4) + lane + 32*j]);
        }
        #pragma unroll
        for (int b = 0; b < B_; b++) {
            float r = warpReduceSum(acc[b]);
            if (lane == 0) s_e[warp*B_ + b] = __expf(r);
        }
    }
    __syncthreads();

    // Zs partial per batch
    if (tid < B_) {
        float z = 0.f;
        #pragma unroll
        for (int k = 0; k < KPER; k++) z += s_e[k*B_ + tid];
        g_Zs_part[kc*B_ + tid] = z;
    }

    // Phase 2: weff partial, 2 columns x 16 batches per thread
    float acc0[B_], acc1[B_];
    #pragma unroll
    for (int b = 0; b < B_; b++) { acc0[b] = 0.f; acc1[b] = 0.f; }
    #pragma unroll
    for (int k = 0; k < KPER; k++) {
        const float* wr = Wsv + (kc*KPER + k)*C_;
        float w0 = wr[tid];
        float w1 = wr[tid + 256];
        #pragma unroll
        for (int b = 0; b < B_; b++) {
            float e = s_e[k*B_ + b];
            acc0[b] = fmaf(e, w0, acc0[b]);
            acc1[b] = fmaf(e, w1, acc1[b]);
        }
    }
    #pragma unroll
    for (int b = 0; b < B_; b++) {
        g_weff_part[(kc*B_ + b)*C_ + tid]       = acc0[b];
        g_weff_part[(kc*B_ + b)*C_ + tid + 256] = acc1[b];
    }
}

// ---------------------------------------------------------------------------
// Pass 2: stream x again -> xw partials (unnormalized, vs exp(cm)) + ctx partials
// Same warp-tiling as pass1; cm held in registers across the channel loop.
// ---------------------------------------------------------------------------
__global__ __launch_bounds__(NT)
void k_pass2(const float* __restrict__ x) {
    const int b    = blockIdx.y;
    const int tile = blockIdx.x >> 4;
    const int g    = blockIdx.x & 15;
    const int tid  = threadIdx.x;
    const int lane = tid & 31, warp = tid >> 5;
    const int wtile = tile*NWARP + warp;

    __shared__ float s_w[CG];
    __shared__ float s_invZs;
    if (tid == 0) {
        float z = 0.f;
        #pragma unroll
        for (int p = 0; p < KCH; p++) z += g_Zs_part[p*B_ + b];
        s_invZs = 1.0f / z;
    }
    __syncthreads();
    if (tid < CG) {
        float s = 0.f;
        #pragma unroll
        for (int p = 0; p < KCH; p++)
            s += g_weff_part[(p*B_ + b)*C_ + g*CG + tid];
        s_w[tid] = s * s_invZs;
    }
    __syncthreads();

    const float4* x4 = reinterpret_cast<const float4*>(x);
    const int fbase = (b*C_ + g*CG)*HW4 + wtile*64 + lane;
    const float4* cmp = reinterpret_cast<const float4*>(g_cm) + b*HW4 + wtile*64 + lane;
    const float4 cm0 = cmp[0];
    const float4 cm1 = cmp[32];

    float4 c0 = make_float4(0.f,0.f,0.f,0.f);
    float4 c1 = make_float4(0.f,0.f,0.f,0.f);
    #pragma unroll 4
    for (int ci = 0; ci < CG; ci++) {
        float4 v0 = x4[fbase + ci*HW4];
        float4 v1 = x4[fbase + ci*HW4 + 32];
        float  w  = s_w[ci];
        c0.x = fmaf(w, v0.x, c0.x); c0.y = fmaf(w, v0.y, c0.y);
        c0.z = fmaf(w, v0.z, c0.z); c0.w = fmaf(w, v0.w, c0.w);
        c1.x = fmaf(w, v1.x, c1.x); c1.y = fmaf(w, v1.y, c1.y);
        c1.z = fmaf(w, v1.z, c1.z); c1.w = fmaf(w, v1.w, c1.w);
        float t = dot4(v0, cm0) + dot4(v1, cm1);
        t = warpReduceSum(t);
        if (lane == 0)
            g_xw_part[(b*C_ + g*CG + ci)*NPART + wtile] = t;
    }
    float4* cxp = reinterpret_cast<float4*>(g_ctx_part) + (b*NCGRP + g)*HW4 + wtile*64 + lane;
    cxp[0]  = c0;
    cxp[32] = c1;
}

// ---------------------------------------------------------------------------
// Red 2 (wide): grid (5, B_), block 256.
// ---------------------------------------------------------------------------
__global__ __launch_bounds__(256)
void k_red2() {
    const int b  = blockIdx.y;
    const int bx = blockIdx.x;
    const int tid = threadIdx.x;

    if (bx < 4) {
        const int pix4 = bx*256 + tid;
        const float4* cp = reinterpret_cast<const float4*>(g_ctx_part);
        float4 s = make_float4(0.f, 0.f, 0.f, 0.f);
        #pragma unroll
        for (int g = 0; g < NCGRP; g++) {
            float4 v = cp[(b*NCGRP + g)*HW4 + pix4];
            s.x += v.x; s.y += v.y; s.z += v.z; s.w += v.w;
        }
        float4 r;
        r.x = 1.0f/(1.0f + __expf(-s.x));
        r.y = 1.0f/(1.0f + __expf(-s.y));
        r.z = 1.0f/(1.0f + __expf(-s.z));
        r.w = 1.0f/(1.0f + __expf(-s.w));
        reinterpret_cast<float4*>(g_sigctx)[b*HW4 + pix4] = r;
    } else {
        for (int c = tid; c < C_; c += 256) {
            const float4* p = reinterpret_cast<const float4*>(
                g_xw_part + (b*C_ + c)*NPART);
            float s = 0.f;
            #pragma unroll
            for (int i = 0; i < NPART/4; i++) {
                float4 v = p[i];
                s += (v.x + v.y) + (v.z + v.w);
            }
            g_xw[b*C_ + c] = s;
        }
    }
}

// ---------------------------------------------------------------------------
// GEMM ctx = Wcv(256x512) @ (xw/Z)(512 x 16). grid 32, block 256.
// ---------------------------------------------------------------------------
__global__ __launch_bounds__(256)
void k_gemm_ctx(const float* __restrict__ Wcv) {
    const int tid = threadIdx.x;
    const int lane = tid & 31, warp = tid >> 5;
    __shared__ __align__(16) float s_xw[B_*C_];      // 32 KB
    __shared__ float s_invZ[B_];

    if (tid < B_)
        s_invZ[tid] = 1.0f / (g_Zc_part[tid*4+0] + g_Zc_part[tid*4+1] +
                              g_Zc_part[tid*4+2] + g_Zc_part[tid*4+3]);
    __syncthreads();

    float4* sm4 = reinterpret_cast<float4*>(s_xw);
    const float4* gm4 = reinterpret_cast<const float4*>(g_xw);
    #pragma unroll
    for (int i = tid; i < B_*C_/4; i += 256) {
        float4 v = gm4[i];
        float z = s_invZ[i >> 7];       // i*4/512
        v.x *= z; v.y *= z; v.z *= z; v.w *= z;
        sm4[i] = v;
    }
    __syncthreads();

    const int row = blockIdx.x*8 + warp;
    const float4* wr = reinterpret_cast<const float4*>(Wcv + row*C_);
    float acc[B_];
    #pragma unroll
    for (int b = 0; b < B_; b++) acc[b] = 0.f;
    #pragma unroll
    for (int j = 0; j < C_/(4*32); j++) {
        float4 w4 = wr[lane + 32*j];
        #pragma unroll
        for (int b = 0; b < B_; b++)
            acc[b] += dot4(w4, sm4[b*(C_/4) + lane + 32*j]);
    }
    #pragma unroll
    for (int b = 0; b < B_; b++) {
        float r = warpReduceSum(acc[b]);
        if (lane == 0) g_ctx[b*INNER_ + row] = r;
    }
}

// ---------------------------------------------------------------------------
// GEMM z = Wcz(512x256) @ ctx(256 x 16). grid 64, block 256.
// ---------------------------------------------------------------------------
__global__ __launch_bounds__(256)
void k_gemm_z(const float* __restrict__ Wcz) {
    const int tid = threadIdx.x;
    const int lane = tid & 31, warp = tid >> 5;
    __shared__ __align__(16) float s_ctx[B_*INNER_];   // 16 KB

    float4* sm4 = reinterpret_cast<float4*>(s_ctx);
    const float4* gm4 = reinterpret_cast<const float4*>(g_ctx);
    #pragma unroll
    for (int i = tid; i < B_*INNER_/4; i += 256) sm4[i] = gm4[i];
    __syncthreads();

    const int row = blockIdx.x*8 + warp;               // [0,512)
    const float4* wr = reinterpret_cast<const float4*>(Wcz + row*INNER_);
    float acc[B_];
    #pragma unroll
    for (int b = 0; b < B_; b++) acc[b] = 0.f;
    #pragma unroll
    for (int j = 0; j < INNER_/(4*32); j++) {
        float4 w4 = wr[lane + 32*j];
        #pragma unroll
        for (int b = 0; b < B_; b++)
            acc[b] += dot4(w4, sm4[b*(INNER_/4) + lane + 32*j]);
    }
    #pragma unroll
    for (int b = 0; b < B_; b++) {
        float r = warpReduceSum(acc[b]);
        if (lane == 0) g_z[b*C_ + row] = r;
    }
}

// ---------------------------------------------------------------------------
// LayerNorm + sigmoid -> mask. grid B_, block 512.
// ---------------------------------------------------------------------------
__global__ __launch_bounds__(512)
void k_ln(const float* __restrict__ gamma, const float* __restrict__ beta) {
    const int b = blockIdx.x;
    const int tid = threadIdx.x;
    float z = g_z[b*C_ + tid];
    float mu  = blockReduceSum(z) * (1.0f/(float)C_);
    float m2  = blockReduceSum(z*z) * (1.0f/(float)C_);
    float var = m2 - mu*mu;
    float zn  = (z - mu) * rsqrtf(var + 1e-5f) * gamma[tid] + beta[tid];
    g_mask[b*C_ + tid] = 1.0f/(1.0f + __expf(-zn));
}

// ---------------------------------------------------------------------------
// Final: out = x * (mask[b,c] + sig_ctx[b,n])
// ---------------------------------------------------------------------------
__global__ __launch_bounds__(256)
void k_final(const float* __restrict__ x, float* __restrict__ out) {
    const float4* x4  = reinterpret_cast<const float4*>(x);
    float4*       o4  = reinterpret_cast<float4*>(out);
    const float4* sc4 = reinterpret_cast<const float4*>(g_sigctx);
    const int total4 = B_*C_*HW4;
    for (int i = blockIdx.x*blockDim.x + threadIdx.x; i < total4;
         i += gridDim.x*blockDim.x) {
        const int n4 = i & (HW4 - 1);
        const int bc = i >> 10;          // b*512 + c
        const int b  = bc >> 9;
        const float  m = g_mask[bc];     // warp-uniform -> single sector
        const float4 s = sc4[(b << 10) + n4];
        float4 v = x4[i];
        float4 r;
        r.x = v.x*(m + s.x);
        r.y = v.y*(m + s.y);
        r.z = v.z*(m + s.z);
        r.w = v.w*(m + s.w);
        o4[i] = r;
    }
}

// ---------------------------------------------------------------------------
// Launch: 8 kernels
// ---------------------------------------------------------------------------
extern "C" void kernel_launch(void* const* d_in, const int* in_sizes, int n_in,
                              void* d_out, int out_size) {
    const float* x     = (const float*)d_in[0];
    const float* Wsq   = (const float*)d_in[1];
    const float* Wsv   = (const float*)d_in[2];
    const float* Wcq   = (const float*)d_in[3];
    const float* Wcv   = (const float*)d_in[4];
    const float* Wcz   = (const float*)d_in[5];
    const float* gamma = (const float*)d_in[6];
    const float* beta  = (const float*)d_in[7];
    float* out = (float*)d_out;

    dim3 gpass(NTILE*NCGRP, B_);   // 64 x 16 = 1024 CTAs
    dim3 gred(5, B_);              // 80 CTAs
    k_pass1   <<<gpass, NT>>>(x, Wcq);
    k_red1    <<<gred, 256>>>();
    k_gemm_aw <<<KCH, 256>>>(Wsq, Wsv);
    k_pass2   <<<gpass, NT>>>(x);
    k_red2    <<<gred, 256>>>();
    k_gemm_ctx<<<32, 256>>>(Wcv);
    k_gemm_z  <<<64, 256>>>(Wcz);
    k_ln      <<<B_, 512>>>(gamma, beta);
    k_final   <<<8192, 256>>>(x, out);
}

// round 15
// speedup vs baseline: 1.1293x; 1.0996x over previous
#include <cuda_runtime.h>

// Problem constants
#define B_      16
#define C_      512
#define HW_     4096
#define INNER_  256
#define HW4     1024        // HW_/4 (float4 units per channel)

// Pass-kernel tiling: lane owns 2 float4 of one channel; warp covers 64 float4
#define NTILE   4           // CTA tiles per (b,g): 4 CTAs x 4 warps = 16 warp-tiles
#define NCGRP   16          // channel groups per batch (32 ch each)
#define CG      32          // C_ / NCGRP
#define NT      128         // threads per pass CTA
#define NWARP   4           // NT/32
#define NPART   16          // warp-tile partials per (b,c)

// weff k-split
#define KCH     32          // k chunks
#define KPER    (INNER_/KCH)   // 8 rows per chunk

// ---------------------------------------------------------------------------
// Scratch (static device globals; fully overwritten every call -> deterministic)
// ---------------------------------------------------------------------------
__device__ __align__(16) float g_cm_part [B_*NCGRP*HW_];   // 4 MB
__device__ __align__(16) float g_ctx_part[B_*NCGRP*HW_];   // 4 MB
__device__ __align__(16) float g_cm      [B_*HW_];         // exp(cm_raw), UNNORMALIZED
__device__ __align__(16) float g_sigctx  [B_*HW_];         // sigmoid(spatial ctx)
__device__ __align__(16) float g_xsum_part[B_*C_*NPART];   // 0.5 MB
__device__ __align__(16) float g_xw_part  [B_*C_*NPART];   // 0.5 MB
__device__ __align__(16) float g_xmean[B_*C_];
__device__ __align__(16) float g_xw   [B_*C_];             // unnormalized x@exp(cm)
__device__ __align__(16) float g_a    [B_*INNER_];         // Wsq@xmean (pre-softmax)
__device__ __align__(16) float g_ctx  [B_*INNER_];         // Wcv@(xw/Z)
__device__ __align__(16) float g_z    [B_*C_];             // Wcz@ctx (pre-LN)
__device__ __align__(16) float g_weff_part[KCH*B_*C_];     // k-chunk partials (UNNORM)
__device__ float g_Zs_part[KCH*B_];                        // spatial-softmax Z partials
__device__ float g_Zc_part[B_*4];                          // channel-softmax Z partials
__device__ float g_mask[B_*C_];

// ---------------------------------------------------------------------------
// Reductions
// ---------------------------------------------------------------------------
__device__ __forceinline__ float warpReduceSum(float v) {
    #pragma unroll
    for (int o = 16; o; o >>= 1) v += __shfl_down_sync(0xffffffffu, v, o);
    return v;
}

__device__ __forceinline__ float blockReduceSum(float v) {
    __shared__ float s[17];
    const int lane = threadIdx.x & 31, wid = threadIdx.x >> 5;
    v = warpReduceSum(v);
    if (lane == 0) s[wid] = v;
    __syncthreads();
    if (wid == 0) {
        float t = (lane < (int)(blockDim.x >> 5)) ? s[lane] : 0.0f;
        #pragma unroll
        for (int o = 8; o; o >>= 1) t += __shfl_down_sync(0xffffffffu, t, o);
        if (lane == 0) s[16] = t;
    }
    __syncthreads();
    float r = s[16];
    __syncthreads();
    return r;
}

__device__ __forceinline__ float dot4(float4 a, float4 b) {
    return fmaf(a.x, b.x, fmaf(a.y, b.y, fmaf(a.z, b.z, a.w * b.w)));
}

// ---------------------------------------------------------------------------
// Pass 1 (primary, no PDL sync needed — reads only graph inputs)
// grid: (NTILE*NCGRP, B_) = (64, 16) = 1024 CTAs, block 128.
// ---------------------------------------------------------------------------
__global__ __launch_bounds__(NT)
void k_pass1(const float* __restrict__ x, const float* __restrict__ Wcq) {
    const int b    = blockIdx.y;
    const int tile = blockIdx.x >> 4;   // /NCGRP  (0..3)
    const int g    = blockIdx.x & 15;
    const int tid  = threadIdx.x;
    const int lane = tid & 31, warp = tid >> 5;
    const int wtile = tile*NWARP + warp;   // 0..15

    __shared__ float s_w[CG];
    if (tid < CG) s_w[tid] = Wcq[g*CG + tid];
    __syncthreads();

    const float4* x4 = reinterpret_cast<const float4*>(x);
    const int fbase = (b*C_ + g*CG)*HW4 + wtile*64 + lane;

    float4 a0 = make_float4(0.f,0.f,0.f,0.f);
    float4 a1 = make_float4(0.f,0.f,0.f,0.f);
    #pragma unroll 4
    for (int ci = 0; ci < CG; ci++) {
        float4 v0 = x4[fbase + ci*HW4];
        float4 v1 = x4[fbase + ci*HW4 + 32];
        float  q  = s_w[ci];
        a0.x = fmaf(q, v0.x, a0.x); a0.y = fmaf(q, v0.y, a0.y);
        a0.z = fmaf(q, v0.z, a0.z); a0.w = fmaf(q, v0.w, a0.w);
        a1.x = fmaf(q, v1.x, a1.x); a1.y = fmaf(q, v1.y, a1.y);
        a1.z = fmaf(q, v1.z, a1.z); a1.w = fmaf(q, v1.w, a1.w);
        float s = ((v0.x+v0.y)+(v0.z+v0.w)) + ((v1.x+v1.y)+(v1.z+v1.w));
        s = warpReduceSum(s);
        if (lane == 0)
            g_xsum_part[(b*C_ + g*CG + ci)*NPART + wtile] = s;
    }
    float4* cmp = reinterpret_cast<float4*>(g_cm_part) + (b*NCGRP + g)*HW4 + wtile*64 + lane;
    cmp[0]  = a0;
    cmp[32] = a1;
}

// ---------------------------------------------------------------------------
// Red 1 (wide): grid (5, B_), block 256.  PDL: sync at top.
// ---------------------------------------------------------------------------
__global__ __launch_bounds__(256)
void k_red1() {
    cudaGridDependencySynchronize();
    const int b  = blockIdx.y;
    const int bx = blockIdx.x;
    const int tid = threadIdx.x;

    if (bx < 4) {
        const int pix4 = bx*256 + tid;       // float4 index in [0,HW4)
        const float4* cp = reinterpret_cast<const float4*>(g_cm_part);
        float4 s = make_float4(0.f, 0.f, 0.f, 0.f);
        #pragma unroll
        for (int g = 0; g < NCGRP; g++) {
            float4 v = cp[(b*NCGRP + g)*HW4 + pix4];
            s.x += v.x; s.y += v.y; s.z += v.z; s.w += v.w;
        }
        float4 e;
        e.x = __expf(s.x); e.y = __expf(s.y);
        e.z = __expf(s.z); e.w = __expf(s.w);
        reinterpret_cast<float4*>(g_cm)[b*HW4 + pix4] = e;
        float zs = blockReduceSum((e.x + e.y) + (e.z + e.w));
        if (tid == 0) g_Zc_part[b*4 + bx] = zs;
    } else {
        for (int c = tid; c < C_; c += 256) {
            const float4* p = reinterpret_cast<const float4*>(
                g_xsum_part + (b*C_ + c)*NPART);
            float s = 0.f;
            #pragma unroll
            for (int i = 0; i < NPART/4; i++) {
                float4 v = p[i];
                s += (v.x + v.y) + (v.z + v.w);
            }
            g_xmean[b*C_ + c] = s * (1.0f/(float)HW_);
        }
    }
}

// ---------------------------------------------------------------------------
// GEMM a = Wsq(256x512) @ xmean(512 x 16). grid 32, block 256.
// PDL prelude: prefetch this warp's Wsq row into registers, THEN sync.
// ---------------------------------------------------------------------------
__global__ __launch_bounds__(256)
void k_gemm_a(const float* __restrict__ Wsq) {
    const int tid = threadIdx.x;
    const int lane = tid & 31, warp = tid >> 5;
    __shared__ __align__(16) float s_xm[B_*C_];      // 32 KB

    // prelude: Wsq is a graph input — load before dependency sync
    const int row = blockIdx.x*8 + warp;             // [0,256)
    const float4* wr = reinterpret_cast<const float4*>(Wsq + row*C_);
    float4 wreg[C_/(4*32)];
    #pragma unroll
    for (int j = 0; j < C_/(4*32); j++) wreg[j] = wr[lane + 32*j];

    cudaGridDependencySynchronize();

    float4* sm4 = reinterpret_cast<float4*>(s_xm);
    const float4* gm4 = reinterpret_cast<const float4*>(g_xmean);
    #pragma unroll
    for (int i = tid; i < B_*C_/4; i += 256) sm4[i] = gm4[i];
    __syncthreads();

    float acc[B_];
    #pragma unroll
    for (int b = 0; b < B_; b++) acc[b] = 0.f;
    #pragma unroll
    for (int j = 0; j < C_/(4*32); j++) {
        #pragma unroll
        for (int b = 0; b < B_; b++)
            acc[b] += dot4(wreg[j], sm4[b*(C_/4) + lane + 32*j]);
    }
    #pragma unroll
    for (int b = 0; b < B_; b++) {
        float r = warpReduceSum(acc[b]);
        if (lane == 0) g_a[b*INNER_ + row] = r;
    }
}

// ---------------------------------------------------------------------------
// weff partials, DEFERRED NORMALIZATION. grid (KCH, B_) = 512 CTAs, block 128.
// PDL prelude: prefetch this CTA's 8 Wsv rows into registers, THEN sync.
// ---------------------------------------------------------------------------
__global__ __launch_bounds__(128)
void k_weff(const float* __restrict__ Wsv) {
    const int kc = blockIdx.x;
    const int b  = blockIdx.y;
    const int tid = threadIdx.x;
    __shared__ __align__(16) float s_e[KPER];

    // prelude: Wsv is a graph input
    const float4* w4 = reinterpret_cast<const float4*>(Wsv);
    float4 wreg[KPER];
    #pragma unroll
    for (int k = 0; k < KPER; k++)
        wreg[k] = w4[(kc*KPER + k)*(C_/4) + tid];

    cudaGridDependencySynchronize();

    if (tid < KPER)
        s_e[tid] = __expf(g_a[b*INNER_ + kc*KPER + tid]);
    __syncthreads();
    if (tid == 0) {
        float z = 0.f;
        #pragma unroll
        for (int k = 0; k < KPER; k++) z += s_e[k];
        g_Zs_part[kc*B_ + b] = z;
    }

    float4 acc = make_float4(0.f, 0.f, 0.f, 0.f);
    #pragma unroll
    for (int k = 0; k < KPER; k++) {
        float a = s_e[k];
        acc.x = fmaf(a, wreg[k].x, acc.x);
        acc.y = fmaf(a, wreg[k].y, acc.y);
        acc.z = fmaf(a, wreg[k].z, acc.z);
        acc.w = fmaf(a, wreg[k].w, acc.w);
    }
    reinterpret_cast<float4*>(g_weff_part)[(kc*B_ + b)*(C_/4) + tid] = acc;
}

// ---------------------------------------------------------------------------
// Pass 2: stream x again -> xw partials + ctx partials.  PDL: sync at top.
// ---------------------------------------------------------------------------
__global__ __launch_bounds__(NT)
void k_pass2(const float* __restrict__ x) {
    cudaGridDependencySynchronize();
    const int b    = blockIdx.y;
    const int tile = blockIdx.x >> 4;
    const int g    = blockIdx.x & 15;
    const int tid  = threadIdx.x;
    const int lane = tid & 31, warp = tid >> 5;
    const int wtile = tile*NWARP + warp;

    __shared__ float s_w[CG];
    __shared__ float s_invZs;
    if (tid == 0) {
        float z = 0.f;
        #pragma unroll
        for (int p = 0; p < KCH; p++) z += g_Zs_part[p*B_ + b];
        s_invZs = 1.0f / z;
    }
    __syncthreads();
    if (tid < CG) {
        float s = 0.f;
        #pragma unroll
        for (int p = 0; p < KCH; p++)
            s += g_weff_part[(p*B_ + b)*C_ + g*CG + tid];
        s_w[tid] = s * s_invZs;
    }
    __syncthreads();

    const float4* x4 = reinterpret_cast<const float4*>(x);
    const int fbase = (b*C_ + g*CG)*HW4 + wtile*64 + lane;
    const float4* cmp = reinterpret_cast<const float4*>(g_cm) + b*HW4 + wtile*64 + lane;
    const float4 cm0 = cmp[0];
    const float4 cm1 = cmp[32];

    float4 c0 = make_float4(0.f,0.f,0.f,0.f);
    float4 c1 = make_float4(0.f,0.f,0.f,0.f);
    #pragma unroll 4
    for (int ci = 0; ci < CG; ci++) {
        float4 v0 = x4[fbase + ci*HW4];
        float4 v1 = x4[fbase + ci*HW4 + 32];
        float  w  = s_w[ci];
        c0.x = fmaf(w, v0.x, c0.x); c0.y = fmaf(w, v0.y, c0.y);
        c0.z = fmaf(w, v0.z, c0.z); c0.w = fmaf(w, v0.w, c0.w);
        c1.x = fmaf(w, v1.x, c1.x); c1.y = fmaf(w, v1.y, c1.y);
        c1.z = fmaf(w, v1.z, c1.z); c1.w = fmaf(w, v1.w, c1.w);
        float t = dot4(v0, cm0) + dot4(v1, cm1);
        t = warpReduceSum(t);
        if (lane == 0)
            g_xw_part[(b*C_ + g*CG + ci)*NPART + wtile] = t;
    }
    float4* cxp = reinterpret_cast<float4*>(g_ctx_part) + (b*NCGRP + g)*HW4 + wtile*64 + lane;
    cxp[0]  = c0;
    cxp[32] = c1;
}

// ---------------------------------------------------------------------------
// Red 2 (wide): grid (5, B_), block 256.  PDL: sync at top.
// ---------------------------------------------------------------------------
__global__ __launch_bounds__(256)
void k_red2() {
    cudaGridDependencySynchronize();
    const int b  = blockIdx.y;
    const int bx = blockIdx.x;
    const int tid = threadIdx.x;

    if (bx < 4) {
        const int pix4 = bx*256 + tid;
        const float4* cp = reinterpret_cast<const float4*>(g_ctx_part);
        float4 s = make_float4(0.f, 0.f, 0.f, 0.f);
        #pragma unroll
        for (int g = 0; g < NCGRP; g++) {
            float4 v = cp[(b*NCGRP + g)*HW4 + pix4];
            s.x += v.x; s.y += v.y; s.z += v.z; s.w += v.w;
        }
        float4 r;
        r.x = 1.0f/(1.0f + __expf(-s.x));
        r.y = 1.0f/(1.0f + __expf(-s.y));
        r.z = 1.0f/(1.0f + __expf(-s.z));
        r.w = 1.0f/(1.0f + __expf(-s.w));
        reinterpret_cast<float4*>(g_sigctx)[b*HW4 + pix4] = r;
    } else {
        for (int c = tid; c < C_; c += 256) {
            const float4* p = reinterpret_cast<const float4*>(
                g_xw_part + (b*C_ + c)*NPART);
            float s = 0.f;
            #pragma unroll
            for (int i = 0; i < NPART/4; i++) {
                float4 v = p[i];
                s += (v.x + v.y) + (v.z + v.w);
            }
            g_xw[b*C_ + c] = s;
        }
    }
}

// ---------------------------------------------------------------------------
// GEMM ctx = Wcv(256x512) @ (xw/Z)(512 x 16). grid 32, block 256.
// PDL prelude: prefetch Wcv row into registers, THEN sync.
// ---------------------------------------------------------------------------
__global__ __launch_bounds__(256)
void k_gemm_ctx(const float* __restrict__ Wcv) {
    const int tid = threadIdx.x;
    const int lane = tid & 31, warp = tid >> 5;
    __shared__ __align__(16) float s_xw[B_*C_];      // 32 KB
    __shared__ float s_invZ[B_];

    // prelude: Wcv is a graph input
    const int row = blockIdx.x*8 + warp;
    const float4* wr = reinterpret_cast<const float4*>(Wcv + row*C_);
    float4 wreg[C_/(4*32)];
    #pragma unroll
    for (int j = 0; j < C_/(4*32); j++) wreg[j] = wr[lane + 32*j];

    cudaGridDependencySynchronize();

    if (tid < B_)
        s_invZ[tid] = 1.0f / (g_Zc_part[tid*4+0] + g_Zc_part[tid*4+1] +
                              g_Zc_part[tid*4+2] + g_Zc_part[tid*4+3]);
    __syncthreads();

    float4* sm4 = reinterpret_cast<float4*>(s_xw);
    const float4* gm4 = reinterpret_cast<const float4*>(g_xw);
    #pragma unroll
    for (int i = tid; i < B_*C_/4; i += 256) {
        float4 v = gm4[i];
        float z = s_invZ[i >> 7];       // i*4/512
        v.x *= z; v.y *= z; v.z *= z; v.w *= z;
        sm4[i] = v;
    }
    __syncthreads();

    float acc[B_];
    #pragma unroll
    for (int b = 0; b < B_; b++) acc[b] = 0.f;
    #pragma unroll
    for (int j = 0; j < C_/(4*32); j++) {
        #pragma unroll
        for (int b = 0; b < B_; b++)
            acc[b] += dot4(wreg[j], sm4[b*(C_/4) + lane + 32*j]);
    }
    #pragma unroll
    for (int b = 0; b < B_; b++) {
        float r = warpReduceSum(acc[b]);
        if (lane == 0) g_ctx[b*INNER_ + row] = r;
    }
}

// ---------------------------------------------------------------------------
// GEMM z = Wcz(512x256) @ ctx(256 x 16). grid 64, block 256.
// PDL prelude: prefetch Wcz row into registers, THEN sync.
// ---------------------------------------------------------------------------
__global__ __launch_bounds__(256)
void k_gemm_z(const float* __restrict__ Wcz) {
    const int tid = threadIdx.x;
    const int lane = tid & 31, warp = tid >> 5;
    __shared__ __align__(16) float s_ctx[B_*INNER_];   // 16 KB

    // prelude: Wcz is a graph input
    const int row = blockIdx.x*8 + warp;               // [0,512)
    const float4* wr = reinterpret_cast<const float4*>(Wcz + row*INNER_);
    float4 wreg[INNER_/(4*32)];
    #pragma unroll
    for (int j = 0; j < INNER_/(4*32); j++) wreg[j] = wr[lane + 32*j];

    cudaGridDependencySynchronize();

    float4* sm4 = reinterpret_cast<float4*>(s_ctx);
    const float4* gm4 = reinterpret_cast<const float4*>(g_ctx);
    #pragma unroll
    for (int i = tid; i < B_*INNER_/4; i += 256) sm4[i] = gm4[i];
    __syncthreads();

    float acc[B_];
    #pragma unroll
    for (int b = 0; b < B_; b++) acc[b] = 0.f;
    #pragma unroll
    for (int j = 0; j < INNER_/(4*32); j++) {
        #pragma unroll
        for (int b = 0; b < B_; b++)
            acc[b] += dot4(wreg[j], sm4[b*(INNER_/4) + lane + 32*j]);
    }
    #pragma unroll
    for (int b = 0; b < B_; b++) {
        float r = warpReduceSum(acc[b]);
        if (lane == 0) g_z[b*C_ + row] = r;
    }
}

// ---------------------------------------------------------------------------
// LayerNorm + sigmoid -> mask. grid B_, block 512.  PDL: prelude gamma/beta.
// ---------------------------------------------------------------------------
__global__ __launch_bounds__(512)
void k_ln(const float* __restrict__ gamma, const float* __restrict__ beta) {
    const int b = blockIdx.x;
    const int tid = threadIdx.x;
    // prelude: gamma/beta are graph inputs
    float gm = gamma[tid];
    float bt = beta[tid];
    cudaGridDependencySynchronize();
    float z = g_z[b*C_ + tid];
    float mu  = blockReduceSum(z) * (1.0f/(float)C_);
    float m2  = blockReduceSum(z*z) * (1.0f/(float)C_);
    float var = m2 - mu*mu;
    float zn  = (z - mu) * rsqrtf(var + 1e-5f) * gm + bt;
    g_mask[b*C_ + tid] = 1.0f/(1.0f + __expf(-zn));
}

// ---------------------------------------------------------------------------
// Final: out = x * (mask[b,c] + sig_ctx[b,n]).  PDL: sync at top.
// ---------------------------------------------------------------------------
__global__ __launch_bounds__(256)
void k_final(const float* __restrict__ x, float* __restrict__ out) {
    cudaGridDependencySynchronize();
    const float4* x4  = reinterpret_cast<const float4*>(x);
    float4*       o4  = reinterpret_cast<float4*>(out);
    const float4* sc4 = reinterpret_cast<const float4*>(g_sigctx);
    const int total4 = B_*C_*HW4;
    for (int i = blockIdx.x*blockDim.x + threadIdx.x; i < total4;
         i += gridDim.x*blockDim.x) {
        const int n4 = i & (HW4 - 1);
        const int bc = i >> 10;          // b*512 + c
        const int b  = bc >> 9;
        const float  m = g_mask[bc];     // warp-uniform -> single sector
        const float4 s = sc4[(b << 10) + n4];
        float4 v = x4[i];
        float4 r;
        r.x = v.x*(m + s.x);
        r.y = v.y*(m + s.y);
        r.z = v.z*(m + s.z);
        r.w = v.w*(m + s.w);
        o4[i] = r;
    }
}

// ---------------------------------------------------------------------------
// Launch: PDL-chained (each secondary may launch during primary's tail;
// cudaGridDependencySynchronize() guards all dependent reads).
// ---------------------------------------------------------------------------
template <typename... ExpT, typename... ActT>
static inline void launch_pdl(dim3 g, dim3 blk, void (*kern)(ExpT...), ActT... args) {
    cudaLaunchConfig_t cfg = {};
    cfg.gridDim = g;
    cfg.blockDim = blk;
    cfg.stream = 0;
    cudaLaunchAttribute attr[1];
    attr[0].id = cudaLaunchAttributeProgrammaticStreamSerialization;
    attr[0].val.programmaticStreamSerializationAllowed = 1;
    cfg.attrs = attr;
    cfg.numAttrs = 1;
    cudaLaunchKernelEx(&cfg, kern, args...);
}

extern "C" void kernel_launch(void* const* d_in, const int* in_sizes, int n_in,
                              void* d_out, int out_size) {
    const float* x     = (const float*)d_in[0];
    const float* Wsq   = (const float*)d_in[1];
    const float* Wsv   = (const float*)d_in[2];
    const float* Wcq   = (const float*)d_in[3];
    const float* Wcv   = (const float*)d_in[4];
    const float* Wcz   = (const float*)d_in[5];
    const float* gamma = (const float*)d_in[6];
    const float* beta  = (const float*)d_in[7];
    float* out = (float*)d_out;

    dim3 gpass(NTILE*NCGRP, B_);   // 64 x 16 = 1024 CTAs
    dim3 gred(5, B_);              // 80 CTAs
    dim3 gweff(KCH, B_);           // 512 CTAs

    k_pass1<<<gpass, NT>>>(x, Wcq);                 // primary: normal launch
    launch_pdl(gred,  dim3(256), k_red1);
    launch_pdl(dim3(32),  dim3(256), k_gemm_a,  Wsq);
    launch_pdl(gweff, dim3(128), k_weff,    Wsv);
    launch_pdl(gpass, dim3(NT),  k_pass2,   x);
    launch_pdl(gred,  dim3(256), k_red2);
    launch_pdl(dim3(32),  dim3(256), k_gemm_ctx, Wcv);
    launch_pdl(dim3(64),  dim3(256), k_gemm_z,   Wcz);
    launch_pdl(dim3(B_),  dim3(512), k_ln,       gamma, beta);
    launch_pdl(dim3(8192), dim3(256), k_final,   x, out);
}